// round 11
// baseline (speedup 1.0000x reference)
#include <cuda_runtime.h>
#include <cuda_bf16.h>
#include <math.h>

// ============================================================================
// SwinDecoder: 3D Swin transformer decoder
//   ZP=HP=WP=32, window (2,8,8) -> N=128 tokens, NW=256 windows, B=2
//   C=192, HEADS=6, hd=32, DEPTH=4, SHIFT=(1,4,4)
// All compute fp32 (rel-err budget 1e-3; fp32 gives ~1e-6).
// ============================================================================

// ---------------- scratch (device globals; no allocation allowed) -----------
__device__ float g_e  [65536 * 192];   // residual stream (b,z,h,w,c)
__device__ float g_ln [65536 * 192];   // LN output (windowed or plain)
__device__ float g_big[65536 * 768];   // im2col A / qkv (576) / mlp hidden (768)
__device__ float g_o  [65536 * 192];   // attention output (windowed)
__device__ float g_peT[128 * 192];     // pe_w transposed to [K=128][N=192]

// ---------------- index helpers ---------------------------------------------
// windowed row r (win*128+n) -> spatial row (b,z,h,w), honoring shift roll.
__device__ __forceinline__ int win2sp(int r, int shifted) {
    int n   = r & 127;
    int win = r >> 7;
    int b   = win >> 8;
    int nw  = win & 255;
    int wz = nw >> 4, wh = (nw >> 2) & 3, ww = nw & 3;
    int lz = n >> 6,  lh = (n >> 3) & 7, lw = n & 7;
    int gz = wz * 2 + lz, gh = wh * 8 + lh, gw = ww * 8 + lw;
    if (shifted) { gz = (gz + 1) & 31; gh = (gh + 4) & 31; gw = (gw + 4) & 31; }
    return ((b * 32 + gz) * 32 + gh) * 32 + gw;
}

// shifted-window mask region id (slices: z {0:30,30:31,31:32}, h/w {0:24,24:28,28:32})
__device__ __forceinline__ int region_cnt(int gz, int gh, int gw) {
    int rz = gz < 30 ? 0 : (gz < 31 ? 1 : 2);
    int rh = gh < 24 ? 0 : (gh < 28 ? 1 : 2);
    int rw = gw < 24 ? 0 : (gw < 28 ? 1 : 2);
    return rz * 9 + rh * 3 + rw;
}

// ---------------- im2col for patch embed ------------------------------------
// A[row=(b,z,h,w)][p=c4*32+i*16+j*4+k] = x[b,c4,2z+i,4h+j,4w+k]
__global__ void im2col_kernel(const float* __restrict__ x, float* __restrict__ A) {
    int i = blockIdx.x * blockDim.x + threadIdx.x;   // 0 .. 65536*128-1
    int p = i & 127;
    int row = i >> 7;
    int c4 = p >> 5, i2 = (p >> 4) & 1, j = (p >> 2) & 3, k = p & 3;
    int b = row >> 15, z = (row >> 10) & 31, h = (row >> 5) & 31, w = row & 31;
    size_t xi = (size_t)b * 4194304 + (size_t)c4 * 1048576
              + (size_t)(2 * z + i2) * 16384 + (size_t)(4 * h + j) * 128 + (4 * w + k);
    A[i] = x[xi];
}

// pe_w (192,128) -> peT (128,192)
__global__ void transpose_pe_kernel(const float* __restrict__ pe_w, float* __restrict__ peT) {
    int i = blockIdx.x * blockDim.x + threadIdx.x;
    if (i < 24576) {
        int e = i >> 7, p = i & 127;
        peT[p * 192 + e] = pe_w[i];
    }
}

// ---------------- LayerNorm (+ optional window-partition gather) -------------
__global__ void ln_kernel(const float* __restrict__ in, float* __restrict__ out,
                          const float* __restrict__ g, const float* __restrict__ b,
                          int windowed, int shifted) {
    __shared__ float red[12];
    int row = blockIdx.x;
    int c = threadIdx.x;                       // 0..191
    int src = windowed ? win2sp(row, shifted) : row;
    float x = in[(size_t)src * 192 + c];
    float s1 = x, s2 = x * x;
    #pragma unroll
    for (int ofs = 16; ofs; ofs >>= 1) {
        s1 += __shfl_xor_sync(0xffffffffu, s1, ofs);
        s2 += __shfl_xor_sync(0xffffffffu, s2, ofs);
    }
    if ((c & 31) == 0) { red[c >> 5] = s1; red[6 + (c >> 5)] = s2; }
    __syncthreads();
    float S1 = 0.f, S2 = 0.f;
    #pragma unroll
    for (int i = 0; i < 6; i++) { S1 += red[i]; S2 += red[6 + i]; }
    float mean = S1 * (1.0f / 192.0f);
    float var  = S2 * (1.0f / 192.0f) - mean * mean;
    float rs = rsqrtf(var + 1e-5f);
    out[(size_t)row * 192 + c] = (x - mean) * rs * g[c] + b[c];
}

// ---------------- generic fp32 GEMM with fused epilogues ---------------------
// C = A[M,K] @ B[K,N] + bias, tile 128x64x16, 256 threads, 8x4 per thread.
// epi: 0=store, 1=gelu-store, 2=out+= (residual), 3=window-reverse scatter +=,
//      4=patch-reconstruction scatter (bias indexed by out-channel).
#define BM 128
#define BN 64
#define BK 16

__global__ __launch_bounds__(256) void gemm_kernel(
    const float* __restrict__ A, const float* __restrict__ B,
    const float* __restrict__ bias, float* __restrict__ out,
    int M, int N, int K, int epi, int shifted)
{
    __shared__ float As[BK][BM + 1];
    __shared__ __align__(16) float Bs[BK][BN];
    int tid = threadIdx.x;
    int bm = blockIdx.y * BM;
    int bn = blockIdx.x * BN;
    int tx = tid & 15;   // col group (x4)
    int ty = tid >> 4;   // row group (x8)

    float acc[8][4];
    #pragma unroll
    for (int i = 0; i < 8; i++)
        #pragma unroll
        for (int j = 0; j < 4; j++) acc[i][j] = 0.f;

    const float* Ab = A + (size_t)bm * K;

    for (int k0 = 0; k0 < K; k0 += BK) {
        // load A tile (128 x 16), store transposed
        #pragma unroll
        for (int li = 0; li < 2; li++) {
            int idx4 = tid + (li << 8);        // 0..511 float4 slots
            int r  = idx4 >> 2;
            int kq = (idx4 & 3) << 2;
            float4 a4 = *(const float4*)(Ab + (size_t)r * K + k0 + kq);
            As[kq + 0][r] = a4.x;
            As[kq + 1][r] = a4.y;
            As[kq + 2][r] = a4.z;
            As[kq + 3][r] = a4.w;
        }
        // load B tile (16 x 64)
        {
            int r = tid >> 4;
            int c = (tid & 15) << 2;
            *(float4*)&Bs[r][c] = *(const float4*)(B + (size_t)(k0 + r) * N + bn + c);
        }
        __syncthreads();
        #pragma unroll
        for (int kk = 0; kk < BK; kk++) {
            float a[8];
            #pragma unroll
            for (int i = 0; i < 8; i++) a[i] = As[kk][ty * 8 + i];
            float4 b4 = *(const float4*)&Bs[kk][tx * 4];
            float bb[4] = {b4.x, b4.y, b4.z, b4.w};
            #pragma unroll
            for (int i = 0; i < 8; i++)
                #pragma unroll
                for (int j = 0; j < 4; j++)
                    acc[i][j] = fmaf(a[i], bb[j], acc[i][j]);
        }
        __syncthreads();
    }

    // epilogue
    #pragma unroll
    for (int i = 0; i < 8; i++) {
        int row = bm + ty * 8 + i;
        int srow = 0;
        if (epi == 3) srow = win2sp(row, shifted);
        #pragma unroll
        for (int j = 0; j < 4; j++) {
            int col = bn + tx * 4 + j;
            float v = acc[i][j];
            if (epi == 0) {
                out[(size_t)row * N + col] = v + bias[col];
            } else if (epi == 1) {
                float t = v + bias[col];
                out[(size_t)row * N + col] = 0.5f * t * (1.0f + erff(t * 0.70710678118654752f));
            } else if (epi == 2) {
                out[(size_t)row * N + col] += v + bias[col];
            } else if (epi == 3) {
                out[(size_t)srow * 192 + col] += v + bias[col];
            } else { // 4: reconstruction scatter; col = o*32 + i2*16 + j2*4 + k2
                int o  = col >> 5, i2 = (col >> 4) & 1, j2 = (col >> 2) & 3, k2 = col & 3;
                int b = row >> 15, z = (row >> 10) & 31, h = (row >> 5) & 31, w = row & 31;
                size_t oi = (size_t)b * 4194304 + (size_t)o * 1048576
                          + (size_t)(2 * z + i2) * 16384 + (size_t)(4 * h + j2) * 128
                          + (4 * w + k2);
                out[oi] = v + bias[o];
            }
        }
    }
}

// ---------------- fused window attention ------------------------------------
// grid (512 windows, 6 heads), 256 threads, dynamic smem 112KB:
//   q,k,v: 128x32 each; s: 128x128 scores.
__global__ __launch_bounds__(256) void attn_kernel(
    const float* __restrict__ qkv, float* __restrict__ o,
    const float* __restrict__ rpb_d, int shifted)
{
    extern __shared__ float sm[];
    float* q = sm;
    float* k = sm + 4096;
    float* v = sm + 8192;
    float* s = sm + 12288;
    int win  = blockIdx.x;
    int head = blockIdx.y;
    int tid  = threadIdx.x;
    int base = win << 7;
    const float scale = 0.17677669529663687f;   // 32^-0.5

    // load q,k,v (coalesced: 32 consecutive floats per (n) per tensor)
    #pragma unroll
    for (int r = 0; r < 16; r++) {
        int idx = tid + (r << 8);
        int n = idx >> 5, dd = idx & 31;
        size_t off = (size_t)(base + n) * 576 + head * 32 + dd;
        q[idx] = qkv[off] * scale;
        k[idx] = qkv[off + 192];
        v[idx] = qkv[off + 384];
    }
    __syncthreads();

    // scores S[n][m] = q[n] . k[m]
    {
        int n  = tid >> 1;
        int mh = (tid & 1) << 6;
        float qr[32];
        const float4* qp = (const float4*)(q + (n << 5));
        #pragma unroll
        for (int dq = 0; dq < 8; dq++) {
            float4 t = qp[dq];
            qr[dq * 4] = t.x; qr[dq * 4 + 1] = t.y; qr[dq * 4 + 2] = t.z; qr[dq * 4 + 3] = t.w;
        }
        #pragma unroll 4
        for (int mm = 0; mm < 64; mm++) {
            int m = mh + mm;
            const float4* kp = (const float4*)(k + (m << 5));
            float acc = 0.f;
            #pragma unroll
            for (int dq = 0; dq < 8; dq++) {
                float4 kv = kp[dq];
                acc = fmaf(kv.x, qr[dq * 4],     acc);
                acc = fmaf(kv.y, qr[dq * 4 + 1], acc);
                acc = fmaf(kv.z, qr[dq * 4 + 2], acc);
                acc = fmaf(kv.w, qr[dq * 4 + 3], acc);
            }
            s[(n << 7) + m] = acc;
        }
    }
    __syncthreads();

    // softmax per row (warp per row) with relative-position bias + shift mask
    {
        int lane = tid & 31, wrp = tid >> 5;
        int nw = win & 255;
        int wz = nw >> 4, wh = (nw >> 2) & 3, ww = nw & 3;
        for (int row = wrp; row < 128; row += 8) {
            int lz = row >> 6, lh = (row >> 3) & 7, lw = row & 7;
            int cn = 0;
            if (shifted) cn = region_cnt(wz * 2 + lz, wh * 8 + lh, ww * 8 + lw);
            float vals[4];
            float mx = -1e30f;
            #pragma unroll
            for (int c = 0; c < 4; c++) {
                int m = lane + (c << 5);
                int mz = m >> 6, mhh = (m >> 3) & 7, mw = m & 7;
                int rpi = (lz - mz + 1) * 225 + (lh - mhh + 7) * 15 + (lw - mw + 7);
                float add = __ldg(rpb_d + rpi * 6 + head);
                if (shifted) {
                    int cm = region_cnt(wz * 2 + mz, wh * 8 + mhh, ww * 8 + mw);
                    if (cm != cn) add -= 100.0f;
                }
                vals[c] = s[(row << 7) + m] + add;
                mx = fmaxf(mx, vals[c]);
            }
            #pragma unroll
            for (int ofs = 16; ofs; ofs >>= 1)
                mx = fmaxf(mx, __shfl_xor_sync(0xffffffffu, mx, ofs));
            float sum = 0.f;
            #pragma unroll
            for (int c = 0; c < 4; c++) { vals[c] = __expf(vals[c] - mx); sum += vals[c]; }
            #pragma unroll
            for (int ofs = 16; ofs; ofs >>= 1)
                sum += __shfl_xor_sync(0xffffffffu, sum, ofs);
            float inv = 1.0f / sum;
            #pragma unroll
            for (int c = 0; c < 4; c++)
                s[(row << 7) + lane + (c << 5)] = vals[c] * inv;
        }
    }
    __syncthreads();

    // O = P @ V ; write o[(win*128+n)*192 + head*32 + d]
    {
        const float4* vp = (const float4*)v;
        #pragma unroll
        for (int r2 = 0; r2 < 4; r2++) {
            int qidx = tid + (r2 << 8);
            int n2 = qidx >> 3;
            int dq = qidx & 7;
            const float* srow = s + (n2 << 7);
            float ax = 0.f, ay = 0.f, az = 0.f, aw = 0.f;
            #pragma unroll 4
            for (int m = 0; m < 128; m++) {
                float sp = srow[m];
                float4 vv = vp[(m << 3) + dq];
                ax = fmaf(sp, vv.x, ax);
                ay = fmaf(sp, vv.y, ay);
                az = fmaf(sp, vv.z, az);
                aw = fmaf(sp, vv.w, aw);
            }
            float4 res = make_float4(ax, ay, az, aw);
            *(float4*)(o + (size_t)(base + n2) * 192 + head * 32 + (dq << 2)) = res;
        }
    }
}

// ---------------- host orchestration -----------------------------------------
extern "C" void kernel_launch(void* const* d_in, const int* in_sizes, int n_in,
                              void* d_out, int out_size) {
    (void)in_sizes; (void)n_in; (void)out_size;
    const float* x       = (const float*)d_in[0];
    const float* pe_w    = (const float*)d_in[1];
    const float* pe_b    = (const float*)d_in[2];
    const float* pe_ln_g = (const float*)d_in[3];
    const float* pe_ln_b = (const float*)d_in[4];
    const float* ln1_g   = (const float*)d_in[5];
    const float* ln1_b   = (const float*)d_in[6];
    const float* qkv_w   = (const float*)d_in[7];
    const float* qkv_b   = (const float*)d_in[8];
    const float* proj_w  = (const float*)d_in[9];
    const float* proj_b  = (const float*)d_in[10];
    const float* rpb     = (const float*)d_in[11];
    const float* ln2_g   = (const float*)d_in[12];
    const float* ln2_b   = (const float*)d_in[13];
    const float* fc1_w   = (const float*)d_in[14];
    const float* fc1_b   = (const float*)d_in[15];
    const float* fc2_w   = (const float*)d_in[16];
    const float* fc2_b   = (const float*)d_in[17];
    const float* rec_w   = (const float*)d_in[18];
    const float* rec_b   = (const float*)d_in[19];
    float* out = (float*)d_out;

    float *e, *ln, *big, *ob, *peT;
    cudaGetSymbolAddress((void**)&e,   g_e);
    cudaGetSymbolAddress((void**)&ln,  g_ln);
    cudaGetSymbolAddress((void**)&big, g_big);
    cudaGetSymbolAddress((void**)&ob,  g_o);
    cudaGetSymbolAddress((void**)&peT, g_peT);

    cudaFuncSetAttribute(attn_kernel, cudaFuncAttributeMaxDynamicSharedMemorySize, 114688);

    // patch embed: im2col -> GEMM (65536 x 192, K=128) -> LN
    im2col_kernel<<<32768, 256>>>(x, big);
    transpose_pe_kernel<<<96, 256>>>(pe_w, peT);
    gemm_kernel<<<dim3(3, 512), 256>>>(big, peT, pe_b, e, 65536, 192, 128, 0, 0);
    ln_kernel<<<65536, 192>>>(e, e, pe_ln_g, pe_ln_b, 0, 0);

    for (int d = 0; d < 4; d++) {
        int sh = d & 1;
        // LN1 + (shift)roll + window partition
        ln_kernel<<<65536, 192>>>(e, ln, ln1_g + d * 192, ln1_b + d * 192, 1, sh);
        // qkv GEMM
        gemm_kernel<<<dim3(9, 512), 256>>>(ln, qkv_w + d * 192 * 576, qkv_b + d * 576,
                                           big, 65536, 576, 192, 0, 0);
        // fused window attention
        attn_kernel<<<dim3(512, 6), 256, 114688>>>(big, ob, rpb + d * 675 * 6, sh);
        // proj GEMM + window reverse + roll back + residual add (scatter +=)
        gemm_kernel<<<dim3(3, 512), 256>>>(ob, proj_w + d * 192 * 192, proj_b + d * 192,
                                           e, 65536, 192, 192, 3, sh);
        // MLP
        ln_kernel<<<65536, 192>>>(e, ln, ln2_g + d * 192, ln2_b + d * 192, 0, 0);
        gemm_kernel<<<dim3(12, 512), 256>>>(ln, fc1_w + d * 192 * 768, fc1_b + d * 768,
                                            big, 65536, 768, 192, 1, 0);
        gemm_kernel<<<dim3(3, 512), 256>>>(big, fc2_w + d * 768 * 192, fc2_b + d * 192,
                                           e, 65536, 192, 768, 2, 0);
    }

    // reconstruction: (65536 x 128, K=192) with scatter + rec_b
    gemm_kernel<<<dim3(2, 512), 256>>>(e, rec_w, rec_b, out, 65536, 128, 192, 4, 0);
}

// round 12
// speedup vs baseline: 1.0016x; 1.0016x over previous
#include <cuda_runtime.h>
#include <cuda_bf16.h>
#include <math.h>

// ============================================================================
// SwinDecoder: 3D Swin transformer decoder
//   ZP=HP=WP=32, window (2,8,8) -> N=128 tokens, NW=256 windows, B=2
//   C=192, HEADS=6, hd=32, DEPTH=4, SHIFT=(1,4,4)
// All compute fp32 (rel-err budget 1e-3; fp32 gives ~1e-6).
// ============================================================================

// ---------------- scratch (device globals; no allocation allowed) -----------
__device__ float g_e  [65536 * 192];   // residual stream (b,z,h,w,c)
__device__ float g_ln [65536 * 192];   // LN output (windowed or plain)
__device__ float g_big[65536 * 768];   // im2col A / qkv (576) / mlp hidden (768)
__device__ float g_o  [65536 * 192];   // attention output (windowed)
__device__ float g_peT[128 * 192];     // pe_w transposed to [K=128][N=192]

// ---------------- index helpers ---------------------------------------------
// windowed row r (win*128+n) -> spatial row (b,z,h,w), honoring shift roll.
__device__ __forceinline__ int win2sp(int r, int shifted) {
    int n   = r & 127;
    int win = r >> 7;
    int b   = win >> 8;
    int nw  = win & 255;
    int wz = nw >> 4, wh = (nw >> 2) & 3, ww = nw & 3;
    int lz = n >> 6,  lh = (n >> 3) & 7, lw = n & 7;
    int gz = wz * 2 + lz, gh = wh * 8 + lh, gw = ww * 8 + lw;
    if (shifted) { gz = (gz + 1) & 31; gh = (gh + 4) & 31; gw = (gw + 4) & 31; }
    return ((b * 32 + gz) * 32 + gh) * 32 + gw;
}

// shifted-window mask region id (slices: z {0:30,30:31,31:32}, h/w {0:24,24:28,28:32})
__device__ __forceinline__ int region_cnt(int gz, int gh, int gw) {
    int rz = gz < 30 ? 0 : (gz < 31 ? 1 : 2);
    int rh = gh < 24 ? 0 : (gh < 28 ? 1 : 2);
    int rw = gw < 24 ? 0 : (gw < 28 ? 1 : 2);
    return rz * 9 + rh * 3 + rw;
}

// ---------------- im2col for patch embed ------------------------------------
// A[row=(b,z,h,w)][p=c4*32+i*16+j*4+k] = x[b,c4,2z+i,4h+j,4w+k]
__global__ void im2col_kernel(const float* __restrict__ x, float* __restrict__ A) {
    int i = blockIdx.x * blockDim.x + threadIdx.x;   // 0 .. 65536*128-1
    int p = i & 127;
    int row = i >> 7;
    int c4 = p >> 5, i2 = (p >> 4) & 1, j = (p >> 2) & 3, k = p & 3;
    int b = row >> 15, z = (row >> 10) & 31, h = (row >> 5) & 31, w = row & 31;
    size_t xi = (size_t)b * 4194304 + (size_t)c4 * 1048576
              + (size_t)(2 * z + i2) * 16384 + (size_t)(4 * h + j) * 128 + (4 * w + k);
    A[i] = x[xi];
}

// pe_w (192,128) -> peT (128,192)
__global__ void transpose_pe_kernel(const float* __restrict__ pe_w, float* __restrict__ peT) {
    int i = blockIdx.x * blockDim.x + threadIdx.x;
    if (i < 24576) {
        int e = i >> 7, p = i & 127;
        peT[p * 192 + e] = pe_w[i];
    }
}

// ---------------- LayerNorm (+ optional window-partition gather) -------------
__global__ void ln_kernel(const float* __restrict__ in, float* __restrict__ out,
                          const float* __restrict__ g, const float* __restrict__ b,
                          int windowed, int shifted) {
    __shared__ float red[12];
    int row = blockIdx.x;
    int c = threadIdx.x;                       // 0..191
    int src = windowed ? win2sp(row, shifted) : row;
    float x = in[(size_t)src * 192 + c];
    float s1 = x, s2 = x * x;
    #pragma unroll
    for (int ofs = 16; ofs; ofs >>= 1) {
        s1 += __shfl_xor_sync(0xffffffffu, s1, ofs);
        s2 += __shfl_xor_sync(0xffffffffu, s2, ofs);
    }
    if ((c & 31) == 0) { red[c >> 5] = s1; red[6 + (c >> 5)] = s2; }
    __syncthreads();
    float S1 = 0.f, S2 = 0.f;
    #pragma unroll
    for (int i = 0; i < 6; i++) { S1 += red[i]; S2 += red[6 + i]; }
    float mean = S1 * (1.0f / 192.0f);
    float var  = S2 * (1.0f / 192.0f) - mean * mean;
    float rs = rsqrtf(var + 1e-5f);
    out[(size_t)row * 192 + c] = (x - mean) * rs * g[c] + b[c];
}

// ---------------- generic fp32 GEMM with fused epilogues ---------------------
// C = A[M,K] @ B[K,N] + bias, tile 128x64x16, 256 threads, 8x4 per thread.
// epi: 0=store, 1=gelu-store, 2=out+= (residual), 3=window-reverse scatter +=,
//      4=patch-reconstruction scatter (bias indexed by out-channel).
#define BM 128
#define BN 64
#define BK 16

__global__ __launch_bounds__(256) void gemm_kernel(
    const float* __restrict__ A, const float* __restrict__ B,
    const float* __restrict__ bias, float* __restrict__ out,
    int M, int N, int K, int epi, int shifted)
{
    __shared__ float As[BK][BM + 1];
    __shared__ __align__(16) float Bs[BK][BN];
    int tid = threadIdx.x;
    int bm = blockIdx.y * BM;
    int bn = blockIdx.x * BN;
    int tx = tid & 15;   // col group (x4)
    int ty = tid >> 4;   // row group (x8)

    float acc[8][4];
    #pragma unroll
    for (int i = 0; i < 8; i++)
        #pragma unroll
        for (int j = 0; j < 4; j++) acc[i][j] = 0.f;

    const float* Ab = A + (size_t)bm * K;

    for (int k0 = 0; k0 < K; k0 += BK) {
        // load A tile (128 x 16), store transposed
        #pragma unroll
        for (int li = 0; li < 2; li++) {
            int idx4 = tid + (li << 8);        // 0..511 float4 slots
            int r  = idx4 >> 2;
            int kq = (idx4 & 3) << 2;
            float4 a4 = *(const float4*)(Ab + (size_t)r * K + k0 + kq);
            As[kq + 0][r] = a4.x;
            As[kq + 1][r] = a4.y;
            As[kq + 2][r] = a4.z;
            As[kq + 3][r] = a4.w;
        }
        // load B tile (16 x 64)
        {
            int r = tid >> 4;
            int c = (tid & 15) << 2;
            *(float4*)&Bs[r][c] = *(const float4*)(B + (size_t)(k0 + r) * N + bn + c);
        }
        __syncthreads();
        #pragma unroll
        for (int kk = 0; kk < BK; kk++) {
            float a[8];
            #pragma unroll
            for (int i = 0; i < 8; i++) a[i] = As[kk][ty * 8 + i];
            float4 b4 = *(const float4*)&Bs[kk][tx * 4];
            float bb[4] = {b4.x, b4.y, b4.z, b4.w};
            #pragma unroll
            for (int i = 0; i < 8; i++)
                #pragma unroll
                for (int j = 0; j < 4; j++)
                    acc[i][j] = fmaf(a[i], bb[j], acc[i][j]);
        }
        __syncthreads();
    }

    // epilogue
    #pragma unroll
    for (int i = 0; i < 8; i++) {
        int row = bm + ty * 8 + i;
        int srow = 0;
        if (epi == 3) srow = win2sp(row, shifted);
        #pragma unroll
        for (int j = 0; j < 4; j++) {
            int col = bn + tx * 4 + j;
            float v = acc[i][j];
            if (epi == 0) {
                out[(size_t)row * N + col] = v + bias[col];
            } else if (epi == 1) {
                float t = v + bias[col];
                out[(size_t)row * N + col] = 0.5f * t * (1.0f + erff(t * 0.70710678118654752f));
            } else if (epi == 2) {
                out[(size_t)row * N + col] += v + bias[col];
            } else if (epi == 3) {
                out[(size_t)srow * 192 + col] += v + bias[col];
            } else { // 4: reconstruction scatter; col = o*32 + i2*16 + j2*4 + k2
                int o  = col >> 5, i2 = (col >> 4) & 1, j2 = (col >> 2) & 3, k2 = col & 3;
                int b = row >> 15, z = (row >> 10) & 31, h = (row >> 5) & 31, w = row & 31;
                size_t oi = (size_t)b * 4194304 + (size_t)o * 1048576
                          + (size_t)(2 * z + i2) * 16384 + (size_t)(4 * h + j2) * 128
                          + (4 * w + k2);
                out[oi] = v + bias[o];
            }
        }
    }
}

// ---------------- fused window attention ------------------------------------
// grid (512 windows, 6 heads), 256 threads, dynamic smem 112KB:
//   q,k,v: 128x32 each; s: 128x128 scores.
__global__ __launch_bounds__(256) void attn_kernel(
    const float* __restrict__ qkv, float* __restrict__ o,
    const float* __restrict__ rpb_d, int shifted)
{
    extern __shared__ float sm[];
    float* q = sm;
    float* k = sm + 4096;
    float* v = sm + 8192;
    float* s = sm + 12288;
    int win  = blockIdx.x;
    int head = blockIdx.y;
    int tid  = threadIdx.x;
    int base = win << 7;
    const float scale = 0.17677669529663687f;   // 32^-0.5

    // load q,k,v (coalesced: 32 consecutive floats per (n) per tensor)
    #pragma unroll
    for (int r = 0; r < 16; r++) {
        int idx = tid + (r << 8);
        int n = idx >> 5, dd = idx & 31;
        size_t off = (size_t)(base + n) * 576 + head * 32 + dd;
        q[idx] = qkv[off] * scale;
        k[idx] = qkv[off + 192];
        v[idx] = qkv[off + 384];
    }
    __syncthreads();

    // scores S[n][m] = q[n] . k[m]
    {
        int n  = tid >> 1;
        int mh = (tid & 1) << 6;
        float qr[32];
        const float4* qp = (const float4*)(q + (n << 5));
        #pragma unroll
        for (int dq = 0; dq < 8; dq++) {
            float4 t = qp[dq];
            qr[dq * 4] = t.x; qr[dq * 4 + 1] = t.y; qr[dq * 4 + 2] = t.z; qr[dq * 4 + 3] = t.w;
        }
        #pragma unroll 4
        for (int mm = 0; mm < 64; mm++) {
            int m = mh + mm;
            const float4* kp = (const float4*)(k + (m << 5));
            float acc = 0.f;
            #pragma unroll
            for (int dq = 0; dq < 8; dq++) {
                float4 kv = kp[dq];
                acc = fmaf(kv.x, qr[dq * 4],     acc);
                acc = fmaf(kv.y, qr[dq * 4 + 1], acc);
                acc = fmaf(kv.z, qr[dq * 4 + 2], acc);
                acc = fmaf(kv.w, qr[dq * 4 + 3], acc);
            }
            s[(n << 7) + m] = acc;
        }
    }
    __syncthreads();

    // softmax per row (warp per row) with relative-position bias + shift mask
    {
        int lane = tid & 31, wrp = tid >> 5;
        int nw = win & 255;
        int wz = nw >> 4, wh = (nw >> 2) & 3, ww = nw & 3;
        for (int row = wrp; row < 128; row += 8) {
            int lz = row >> 6, lh = (row >> 3) & 7, lw = row & 7;
            int cn = 0;
            if (shifted) cn = region_cnt(wz * 2 + lz, wh * 8 + lh, ww * 8 + lw);
            float vals[4];
            float mx = -1e30f;
            #pragma unroll
            for (int c = 0; c < 4; c++) {
                int m = lane + (c << 5);
                int mz = m >> 6, mhh = (m >> 3) & 7, mw = m & 7;
                int rpi = (lz - mz + 1) * 225 + (lh - mhh + 7) * 15 + (lw - mw + 7);
                float add = __ldg(rpb_d + rpi * 6 + head);
                if (shifted) {
                    int cm = region_cnt(wz * 2 + mz, wh * 8 + mhh, ww * 8 + mw);
                    if (cm != cn) add -= 100.0f;
                }
                vals[c] = s[(row << 7) + m] + add;
                mx = fmaxf(mx, vals[c]);
            }
            #pragma unroll
            for (int ofs = 16; ofs; ofs >>= 1)
                mx = fmaxf(mx, __shfl_xor_sync(0xffffffffu, mx, ofs));
            float sum = 0.f;
            #pragma unroll
            for (int c = 0; c < 4; c++) { vals[c] = __expf(vals[c] - mx); sum += vals[c]; }
            #pragma unroll
            for (int ofs = 16; ofs; ofs >>= 1)
                sum += __shfl_xor_sync(0xffffffffu, sum, ofs);
            float inv = 1.0f / sum;
            #pragma unroll
            for (int c = 0; c < 4; c++)
                s[(row << 7) + lane + (c << 5)] = vals[c] * inv;
        }
    }
    __syncthreads();

    // O = P @ V ; write o[(win*128+n)*192 + head*32 + d]
    {
        const float4* vp = (const float4*)v;
        #pragma unroll
        for (int r2 = 0; r2 < 4; r2++) {
            int qidx = tid + (r2 << 8);
            int n2 = qidx >> 3;
            int dq = qidx & 7;
            const float* srow = s + (n2 << 7);
            float ax = 0.f, ay = 0.f, az = 0.f, aw = 0.f;
            #pragma unroll 4
            for (int m = 0; m < 128; m++) {
                float sp = srow[m];
                float4 vv = vp[(m << 3) + dq];
                ax = fmaf(sp, vv.x, ax);
                ay = fmaf(sp, vv.y, ay);
                az = fmaf(sp, vv.z, az);
                aw = fmaf(sp, vv.w, aw);
            }
            float4 res = make_float4(ax, ay, az, aw);
            *(float4*)(o + (size_t)(base + n2) * 192 + head * 32 + (dq << 2)) = res;
        }
    }
}

// ---------------- host orchestration -----------------------------------------
extern "C" void kernel_launch(void* const* d_in, const int* in_sizes, int n_in,
                              void* d_out, int out_size) {
    (void)in_sizes; (void)n_in; (void)out_size;
    const float* x       = (const float*)d_in[0];
    const float* pe_w    = (const float*)d_in[1];
    const float* pe_b    = (const float*)d_in[2];
    const float* pe_ln_g = (const float*)d_in[3];
    const float* pe_ln_b = (const float*)d_in[4];
    const float* ln1_g   = (const float*)d_in[5];
    const float* ln1_b   = (const float*)d_in[6];
    const float* qkv_w   = (const float*)d_in[7];
    const float* qkv_b   = (const float*)d_in[8];
    const float* proj_w  = (const float*)d_in[9];
    const float* proj_b  = (const float*)d_in[10];
    const float* rpb     = (const float*)d_in[11];
    const float* ln2_g   = (const float*)d_in[12];
    const float* ln2_b   = (const float*)d_in[13];
    const float* fc1_w   = (const float*)d_in[14];
    const float* fc1_b   = (const float*)d_in[15];
    const float* fc2_w   = (const float*)d_in[16];
    const float* fc2_b   = (const float*)d_in[17];
    const float* rec_w   = (const float*)d_in[18];
    const float* rec_b   = (const float*)d_in[19];
    float* out = (float*)d_out;

    float *e, *ln, *big, *ob, *peT;
    cudaGetSymbolAddress((void**)&e,   g_e);
    cudaGetSymbolAddress((void**)&ln,  g_ln);
    cudaGetSymbolAddress((void**)&big, g_big);
    cudaGetSymbolAddress((void**)&ob,  g_o);
    cudaGetSymbolAddress((void**)&peT, g_peT);

    cudaFuncSetAttribute(attn_kernel, cudaFuncAttributeMaxDynamicSharedMemorySize, 114688);

    // patch embed: im2col -> GEMM (65536 x 192, K=128) -> LN
    im2col_kernel<<<32768, 256>>>(x, big);
    transpose_pe_kernel<<<96, 256>>>(pe_w, peT);
    gemm_kernel<<<dim3(3, 512), 256>>>(big, peT, pe_b, e, 65536, 192, 128, 0, 0);
    ln_kernel<<<65536, 192>>>(e, e, pe_ln_g, pe_ln_b, 0, 0);

    for (int d = 0; d < 4; d++) {
        int sh = d & 1;
        // LN1 + (shift)roll + window partition
        ln_kernel<<<65536, 192>>>(e, ln, ln1_g + d * 192, ln1_b + d * 192, 1, sh);
        // qkv GEMM
        gemm_kernel<<<dim3(9, 512), 256>>>(ln, qkv_w + d * 192 * 576, qkv_b + d * 576,
                                           big, 65536, 576, 192, 0, 0);
        // fused window attention
        attn_kernel<<<dim3(512, 6), 256, 114688>>>(big, ob, rpb + d * 675 * 6, sh);
        // proj GEMM + window reverse + roll back + residual add (scatter +=)
        gemm_kernel<<<dim3(3, 512), 256>>>(ob, proj_w + d * 192 * 192, proj_b + d * 192,
                                           e, 65536, 192, 192, 3, sh);
        // MLP
        ln_kernel<<<65536, 192>>>(e, ln, ln2_g + d * 192, ln2_b + d * 192, 0, 0);
        gemm_kernel<<<dim3(12, 512), 256>>>(ln, fc1_w + d * 192 * 768, fc1_b + d * 768,
                                            big, 65536, 768, 192, 1, 0);
        gemm_kernel<<<dim3(3, 512), 256>>>(big, fc2_w + d * 768 * 192, fc2_b + d * 192,
                                           e, 65536, 192, 768, 2, 0);
    }

    // reconstruction: (65536 x 128, K=192) with scatter + rec_b
    gemm_kernel<<<dim3(2, 512), 256>>>(e, rec_w, rec_b, out, 65536, 128, 192, 4, 0);
}